// round 1
// baseline (speedup 1.0000x reference)
#include <cuda_runtime.h>
#include <cstdint>

#define BQ 16
#define CC 512
#define NN 1024
#define NH 8
#define HD 64
#define NG 32
#define CPG 16
#define EPSV 1e-5f

// Scratch (device globals: allocation-free per harness rules)
__device__ float g_xn[(size_t)BQ * CC * NN];        // 33.5 MB
__device__ float g_qkv[(size_t)BQ * 3 * CC * NN];   // 100 MB
__device__ float g_att[(size_t)BQ * CC * NN];       // 33.5 MB

// ---------------------------------------------------------------------------
// GroupNorm: one CTA per (b, g). 16 channels x 1024 spatial = 16384 floats.
// ---------------------------------------------------------------------------
__global__ __launch_bounds__(256) void groupnorm_kernel(
    const float* __restrict__ x, const float* __restrict__ gamma,
    const float* __restrict__ beta, float* __restrict__ xn) {
    const int b = blockIdx.x / NG;
    const int g = blockIdx.x % NG;
    const float* px = x + ((size_t)b * CC + g * CPG) * NN;
    float* po = xn + ((size_t)b * CC + g * CPG) * NN;
    const int M = CPG * NN;  // 16384

    float s = 0.f, ss = 0.f;
    for (int i = threadIdx.x; i < M / 4; i += blockDim.x) {
        float4 v = ((const float4*)px)[i];
        s += v.x + v.y + v.z + v.w;
        ss += v.x * v.x + v.y * v.y + v.z * v.z + v.w * v.w;
    }
    __shared__ float rs[32], rss[32];
#pragma unroll
    for (int o = 16; o; o >>= 1) {
        s += __shfl_xor_sync(0xffffffffu, s, o);
        ss += __shfl_xor_sync(0xffffffffu, ss, o);
    }
    int wid = threadIdx.x / 32, lid = threadIdx.x % 32;
    if (lid == 0) { rs[wid] = s; rss[wid] = ss; }
    __syncthreads();
    if (wid == 0) {
        s = (lid < (int)(blockDim.x / 32)) ? rs[lid] : 0.f;
        ss = (lid < (int)(blockDim.x / 32)) ? rss[lid] : 0.f;
#pragma unroll
        for (int o = 16; o; o >>= 1) {
            s += __shfl_xor_sync(0xffffffffu, s, o);
            ss += __shfl_xor_sync(0xffffffffu, ss, o);
        }
        if (lid == 0) { rs[0] = s; rss[0] = ss; }
    }
    __syncthreads();
    const float mean = rs[0] / (float)M;
    const float var = rss[0] / (float)M - mean * mean;
    const float rstd = rsqrtf(var + EPSV);

    for (int i = threadIdx.x; i < M / 4; i += blockDim.x) {
        int c = i / (NN / 4);  // channel within group
        float ga = gamma[g * CPG + c] * rstd;
        float be = beta[g * CPG + c];
        float4 v = ((const float4*)px)[i];
        float4 o;
        o.x = (v.x - mean) * ga + be;
        o.y = (v.y - mean) * ga + be;
        o.z = (v.z - mean) * ga + be;
        o.w = (v.w - mean) * ga + be;
        ((float4*)po)[i] = o;
    }
}

// ---------------------------------------------------------------------------
// Tiled fp32 GEMM: out[b, m, n] = sum_k W[m,k] * X[b,k,n] + bias[m] (+ res)
// BM=BN=128, BK=8, 256 threads, 8x8 per thread.
// grid: (NN/128, O/128, B)
// ---------------------------------------------------------------------------
template <bool RES>
__global__ __launch_bounds__(256) void gemm_kernel(
    const float* __restrict__ W, const float* __restrict__ bias,
    const float* __restrict__ X, const float* __restrict__ res,
    float* __restrict__ out, int O) {
    __shared__ float As[8][128];
    __shared__ float Bs[8][128];

    const int b = blockIdx.z;
    const float* Xb = X + (size_t)b * CC * NN;
    float* outb = out + (size_t)b * O * NN;
    const int m0 = blockIdx.y * 128, n0 = blockIdx.x * 128;
    const int tid = threadIdx.x;
    const int tx = tid % 16, ty = tid / 16;

    const int arow = tid / 2, acol = (tid % 2) * 4;
    const int brow = tid / 32, bcol = (tid % 32) * 4;

    float acc[8][8];
#pragma unroll
    for (int i = 0; i < 8; i++)
#pragma unroll
        for (int j = 0; j < 8; j++) acc[i][j] = 0.f;

    for (int k0 = 0; k0 < CC; k0 += 8) {
        float4 a = *(const float4*)&W[(size_t)(m0 + arow) * CC + k0 + acol];
        As[acol + 0][arow] = a.x;
        As[acol + 1][arow] = a.y;
        As[acol + 2][arow] = a.z;
        As[acol + 3][arow] = a.w;
        *(float4*)&Bs[brow][bcol] =
            *(const float4*)&Xb[(size_t)(k0 + brow) * NN + n0 + bcol];
        __syncthreads();
#pragma unroll
        for (int k = 0; k < 8; k++) {
            float fa[8], fb[8];
            *(float4*)&fa[0] = *(float4*)&As[k][ty * 8];
            *(float4*)&fa[4] = *(float4*)&As[k][ty * 8 + 4];
            *(float4*)&fb[0] = *(float4*)&Bs[k][tx * 8];
            *(float4*)&fb[4] = *(float4*)&Bs[k][tx * 8 + 4];
#pragma unroll
            for (int i = 0; i < 8; i++)
#pragma unroll
                for (int j = 0; j < 8; j++) acc[i][j] += fa[i] * fb[j];
        }
        __syncthreads();
    }

#pragma unroll
    for (int i = 0; i < 8; i++) {
        const int m = m0 + ty * 8 + i;
        const float bv = bias[m];
#pragma unroll
        for (int j = 0; j < 8; j += 4) {
            const int n = n0 + tx * 8 + j;
            float4 r;
            r.x = acc[i][j + 0] + bv;
            r.y = acc[i][j + 1] + bv;
            r.z = acc[i][j + 2] + bv;
            r.w = acc[i][j + 3] + bv;
            if (RES) {
                float4 rv = *(const float4*)&res[((size_t)b * O + m) * NN + n];
                r.x += rv.x; r.y += rv.y; r.z += rv.z; r.w += rv.w;
            }
            *(float4*)&outb[(size_t)m * NN + n] = r;
        }
    }
}

// ---------------------------------------------------------------------------
// Flash attention fp32. CTA = (qblock, head, batch). BM=BN=128, D=64.
// qkv layout per batch: [3C, N]; q rows h*64.., k at +C*N, v at +2C*N.
// ---------------------------------------------------------------------------
#define QST 132   // padded stride for Qs/Ks/Vs/Ps rows

__global__ __launch_bounds__(256, 1) void attn_kernel(
    const float* __restrict__ qkv, float* __restrict__ out) {
    extern __shared__ float sm[];
    float* Qs = sm;                 // [64][QST]
    float* Ks = Qs + 64 * QST;      // [64][QST]
    float* Vs = Ks + 64 * QST;      // [64][QST]
    float* Ps = Vs + 64 * QST;      // [128][QST]

    const int qb = blockIdx.x, h = blockIdx.y, b = blockIdx.z;
    const float* qg = qkv + ((size_t)b * 3 * CC + h * HD) * NN;
    const float* kg = qg + (size_t)CC * NN;
    const float* vg = kg + (size_t)CC * NN;

    const int tid = threadIdx.x;
    const int tx = tid % 16, ty = tid / 16;
    const float scale = 0.125f;  // 1/sqrt(64)

    // load Q tile (64 x 128), pre-scaled
    for (int i = tid; i < 64 * 32; i += 256) {
        int d = i / 32, c4 = (i % 32) * 4;
        float4 v = *(const float4*)&qg[(size_t)d * NN + qb * 128 + c4];
        v.x *= scale; v.y *= scale; v.z *= scale; v.w *= scale;
        *(float4*)&Qs[d * QST + c4] = v;
    }

    float m_i[8], l_i[8], o[8][4];
#pragma unroll
    for (int i = 0; i < 8; i++) {
        m_i[i] = -1e30f; l_i[i] = 0.f;
#pragma unroll
        for (int j = 0; j < 4; j++) o[i][j] = 0.f;
    }

    for (int kb = 0; kb < 8; kb++) {
        __syncthreads();  // protects Ks/Vs (prev iter) and Q (first iter)
        for (int i = tid; i < 64 * 32; i += 256) {
            int d = i / 32, c4 = (i % 32) * 4;
            *(float4*)&Ks[d * QST + c4] =
                *(const float4*)&kg[(size_t)d * NN + kb * 128 + c4];
            *(float4*)&Vs[d * QST + c4] =
                *(const float4*)&vg[(size_t)d * NN + kb * 128 + c4];
        }
        __syncthreads();

        // S = Q^T K (fragment 8x8 per thread)
        float s[8][8];
#pragma unroll
        for (int i = 0; i < 8; i++)
#pragma unroll
            for (int j = 0; j < 8; j++) s[i][j] = 0.f;
#pragma unroll 8
        for (int d = 0; d < 64; d++) {
            float fa[8], fb[8];
            *(float4*)&fa[0] = *(float4*)&Qs[d * QST + ty * 8];
            *(float4*)&fa[4] = *(float4*)&Qs[d * QST + ty * 8 + 4];
            *(float4*)&fb[0] = *(float4*)&Ks[d * QST + tx * 8];
            *(float4*)&fb[4] = *(float4*)&Ks[d * QST + tx * 8 + 4];
#pragma unroll
            for (int i = 0; i < 8; i++)
#pragma unroll
                for (int j = 0; j < 8; j++) s[i][j] += fa[i] * fb[j];
        }

        // online softmax per owned row; 16 lanes (same ty) cooperate via shfl
#pragma unroll
        for (int i = 0; i < 8; i++) {
            float rm = s[i][0];
#pragma unroll
            for (int j = 1; j < 8; j++) rm = fmaxf(rm, s[i][j]);
            rm = fmaxf(rm, __shfl_xor_sync(0xffffffffu, rm, 1, 16));
            rm = fmaxf(rm, __shfl_xor_sync(0xffffffffu, rm, 2, 16));
            rm = fmaxf(rm, __shfl_xor_sync(0xffffffffu, rm, 4, 16));
            rm = fmaxf(rm, __shfl_xor_sync(0xffffffffu, rm, 8, 16));
            float mnew = fmaxf(m_i[i], rm);
            float alpha = __expf(m_i[i] - mnew);
            m_i[i] = mnew;
            float rsum = 0.f;
#pragma unroll
            for (int j = 0; j < 8; j++) {
                s[i][j] = __expf(s[i][j] - mnew);
                rsum += s[i][j];
            }
            rsum += __shfl_xor_sync(0xffffffffu, rsum, 1, 16);
            rsum += __shfl_xor_sync(0xffffffffu, rsum, 2, 16);
            rsum += __shfl_xor_sync(0xffffffffu, rsum, 4, 16);
            rsum += __shfl_xor_sync(0xffffffffu, rsum, 8, 16);
            l_i[i] = l_i[i] * alpha + rsum;
#pragma unroll
            for (int j = 0; j < 4; j++) o[i][j] *= alpha;
            *(float4*)&Ps[(ty * 8 + i) * QST + tx * 8] =
                make_float4(s[i][0], s[i][1], s[i][2], s[i][3]);
            *(float4*)&Ps[(ty * 8 + i) * QST + tx * 8 + 4] =
                make_float4(s[i][4], s[i][5], s[i][6], s[i][7]);
        }
        __syncthreads();

        // O += P @ V^T. Thread owns qi = ty*8+i, d = tx + 16*j
#pragma unroll 4
        for (int kj = 0; kj < 128; kj++) {
            float vr[4];
#pragma unroll
            for (int j = 0; j < 4; j++) vr[j] = Vs[(tx + 16 * j) * QST + kj];
#pragma unroll
            for (int i = 0; i < 8; i++) {
                float p = Ps[(ty * 8 + i) * QST + kj];
#pragma unroll
                for (int j = 0; j < 4; j++) o[i][j] += p * vr[j];
            }
        }
    }

    // epilogue: normalize and write out[b, h*64+d, qb*128+qi]
    float* og = out + ((size_t)b * CC + h * HD) * NN + qb * 128;
#pragma unroll
    for (int i = 0; i < 8; i++) {
        float inv = 1.f / l_i[i];
        int qi = ty * 8 + i;
#pragma unroll
        for (int j = 0; j < 4; j++) {
            og[(size_t)(tx + 16 * j) * NN + qi] = o[i][j] * inv;
        }
    }
}

// ---------------------------------------------------------------------------
extern "C" void kernel_launch(void* const* d_in, const int* in_sizes, int n_in,
                              void* d_out, int out_size) {
    const float* x = (const float*)d_in[0];
    const float* gamma = (const float*)d_in[1];
    const float* beta = (const float*)d_in[2];
    const float* qkv_w = (const float*)d_in[3];
    const float* qkv_b = (const float*)d_in[4];
    const float* proj_w = (const float*)d_in[5];
    const float* proj_b = (const float*)d_in[6];
    float* out = (float*)d_out;

    float *xn, *qkv, *att;
    cudaGetSymbolAddress((void**)&xn, g_xn);
    cudaGetSymbolAddress((void**)&qkv, g_qkv);
    cudaGetSymbolAddress((void**)&att, g_att);

    // 1. GroupNorm
    groupnorm_kernel<<<BQ * NG, 256>>>(x, gamma, beta, xn);

    // 2. QKV GEMM: [1536,512] @ [B,512,1024]
    dim3 gq(NN / 128, (3 * CC) / 128, BQ);
    gemm_kernel<false><<<gq, 256>>>(qkv_w, qkv_b, xn, nullptr, qkv, 3 * CC);

    // 3. Flash attention
    size_t shmem = (size_t)(3 * 64 * QST + 128 * QST) * sizeof(float);
    cudaFuncSetAttribute(attn_kernel,
                         cudaFuncAttributeMaxDynamicSharedMemorySize,
                         (int)shmem);
    attn_kernel<<<dim3(NN / 128, NH, BQ), 256, shmem>>>(qkv, att);

    // 4. Proj GEMM + residual
    dim3 gp(NN / 128, CC / 128, BQ);
    gemm_kernel<true><<<gp, 256>>>(proj_w, proj_b, att, x, out, CC);
}

// round 3
// speedup vs baseline: 1.4712x; 1.4712x over previous
#include <cuda_runtime.h>
#include <cstdint>

#define BQ 16
#define CC 512
#define NN 1024
#define NH 8
#define HD 64
#define NG 32
#define CPG 16
#define EPSV 1e-5f

// ---------------------------------------------------------------------------
// mma.sync helpers (base PTX, works on compute_103 virtual arch)
// ---------------------------------------------------------------------------
__device__ __forceinline__ uint32_t f2tf32(float f) {
    uint32_t r;
    asm("cvt.rna.tf32.f32 %0, %1;" : "=r"(r) : "f"(f));
    return r;
}
__device__ __forceinline__ void mma_tf32(float* c, const uint32_t* a,
                                         const uint32_t* b) {
    asm volatile(
        "mma.sync.aligned.m16n8k8.row.col.f32.tf32.tf32.f32 "
        "{%0,%1,%2,%3}, {%4,%5,%6,%7}, {%8,%9}, {%0,%1,%2,%3};"
        : "+f"(c[0]), "+f"(c[1]), "+f"(c[2]), "+f"(c[3])
        : "r"(a[0]), "r"(a[1]), "r"(a[2]), "r"(a[3]), "r"(b[0]), "r"(b[1]));
}

// ---------------------------------------------------------------------------
// Scratch
// ---------------------------------------------------------------------------
__device__ float g_xnT[(size_t)BQ * NN * CC];       // [B,N,C]
__device__ float g_qkv[(size_t)BQ * 3 * CC * NN];   // [B,3C,N]
__device__ float g_attT[(size_t)BQ * NN * CC];      // [B,N,C]

// ---------------------------------------------------------------------------
// GroupNorm: one CTA per (b, g). Output TRANSPOSED: xnT[b][n][c].
// ---------------------------------------------------------------------------
__global__ __launch_bounds__(256) void groupnorm_kernel(
    const float* __restrict__ x, const float* __restrict__ gamma,
    const float* __restrict__ beta, float* __restrict__ xnT) {
    const int b = blockIdx.x / NG;
    const int g = blockIdx.x % NG;
    const float* px = x + ((size_t)b * CC + g * CPG) * NN;
    const int M = CPG * NN;

    float s = 0.f, ss = 0.f;
    for (int i = threadIdx.x; i < M / 4; i += blockDim.x) {
        float4 v = ((const float4*)px)[i];
        s += v.x + v.y + v.z + v.w;
        ss += v.x * v.x + v.y * v.y + v.z * v.z + v.w * v.w;
    }
    __shared__ float rs[32], rss[32];
    __shared__ float tile[16 * 129];
#pragma unroll
    for (int o = 16; o; o >>= 1) {
        s += __shfl_xor_sync(0xffffffffu, s, o);
        ss += __shfl_xor_sync(0xffffffffu, ss, o);
    }
    int wid = threadIdx.x / 32, lid = threadIdx.x % 32;
    if (lid == 0) { rs[wid] = s; rss[wid] = ss; }
    __syncthreads();
    if (wid == 0) {
        s = (lid < 8) ? rs[lid] : 0.f;
        ss = (lid < 8) ? rss[lid] : 0.f;
#pragma unroll
        for (int o = 16; o; o >>= 1) {
            s += __shfl_xor_sync(0xffffffffu, s, o);
            ss += __shfl_xor_sync(0xffffffffu, ss, o);
        }
        if (lid == 0) { rs[0] = s; rss[0] = ss; }
    }
    __syncthreads();
    const float mean = rs[0] / (float)M;
    const float var = rss[0] / (float)M - mean * mean;
    const float rstd = rsqrtf(var + EPSV);

    for (int n0 = 0; n0 < NN; n0 += 128) {
        __syncthreads();
#pragma unroll
        for (int rep = 0; rep < 8; rep++) {
            int idx = rep * 256 + threadIdx.x;
            int c = idx >> 7, n = idx & 127;
            float ga = gamma[g * CPG + c] * rstd;
            float be = beta[g * CPG + c];
            float v = px[(size_t)c * NN + n0 + n];
            tile[c * 129 + n] = (v - mean) * ga + be;
        }
        __syncthreads();
#pragma unroll
        for (int rep = 0; rep < 8; rep++) {
            int idx = rep * 256 + threadIdx.x;
            int n = idx >> 4, c = idx & 15;
            xnT[((size_t)b * NN + n0 + n) * CC + g * CPG + c] = tile[c * 129 + n];
        }
    }
}

// ---------------------------------------------------------------------------
// TF32 mma.sync GEMM: out[b,m,n] = sum_k W[m,k]*XT[b,n,k] + bias[m] (+res)
// CTA 128x128, BK=16, 8 warps (2m x 4n), warp tile 64x32.
// grid (NN/128, O/128, B), 256 threads.
// ---------------------------------------------------------------------------
#define BK 16
#define APAD 20  // floats per SMEM row (conflict-free for frag loads)

template <bool RES>
__global__ __launch_bounds__(256, 2) void gemm_mma(
    const float* __restrict__ W, const float* __restrict__ bias,
    const float* __restrict__ XT, const float* __restrict__ res,
    float* __restrict__ out, int O) {
    __shared__ uint32_t As[2][128 * APAD];
    __shared__ uint32_t Bs[2][128 * APAD];

    const int tid = threadIdx.x;
    const int wid = tid >> 5, lane = tid & 31;
    const int g = lane >> 2, tig = lane & 3;
    const int wm = wid >> 2, wn = wid & 3;  // warp grid 2x4
    const int b = blockIdx.z, n0 = blockIdx.x * 128, m0 = blockIdx.y * 128;
    const float* Xb = XT + (size_t)b * NN * CC;

    // global load mapping: 512 float4 per tile, 2 per thread
    const int lm0 = tid >> 2, lk0 = (tid & 3) * 4;        // i = tid
    const int lm1 = (tid + 256) >> 2, lk1 = lk0;          // i = tid + 256

    float acc[4][4][4];
#pragma unroll
    for (int i = 0; i < 4; i++)
#pragma unroll
        for (int j = 0; j < 4; j++)
#pragma unroll
            for (int e = 0; e < 4; e++) acc[i][j][e] = 0.f;

    const float* Wp = W + (size_t)m0 * CC;
    const float* Xp = Xb + (size_t)n0 * CC;

    // preload chunk 0
    {
        float4 a0 = *(const float4*)&Wp[(size_t)lm0 * CC + lk0];
        float4 a1 = *(const float4*)&Wp[(size_t)lm1 * CC + lk1];
        float4 b0 = *(const float4*)&Xp[(size_t)lm0 * CC + lk0];
        float4 b1 = *(const float4*)&Xp[(size_t)lm1 * CC + lk1];
        uint32_t* pa0 = &As[0][lm0 * APAD + lk0];
        pa0[0] = f2tf32(a0.x); pa0[1] = f2tf32(a0.y); pa0[2] = f2tf32(a0.z); pa0[3] = f2tf32(a0.w);
        uint32_t* pa1 = &As[0][lm1 * APAD + lk1];
        pa1[0] = f2tf32(a1.x); pa1[1] = f2tf32(a1.y); pa1[2] = f2tf32(a1.z); pa1[3] = f2tf32(a1.w);
        uint32_t* pb0 = &Bs[0][lm0 * APAD + lk0];
        pb0[0] = f2tf32(b0.x); pb0[1] = f2tf32(b0.y); pb0[2] = f2tf32(b0.z); pb0[3] = f2tf32(b0.w);
        uint32_t* pb1 = &Bs[0][lm1 * APAD + lk1];
        pb1[0] = f2tf32(b1.x); pb1[1] = f2tf32(b1.y); pb1[2] = f2tf32(b1.z); pb1[3] = f2tf32(b1.w);
    }
    __syncthreads();

    const int NKT = CC / BK;  // 32
    for (int kt = 0; kt < NKT; kt++) {
        const int cur = kt & 1, nxt = cur ^ 1;
        float4 a0, a1, b0, b1;
        if (kt + 1 < NKT) {
            const int k0 = (kt + 1) * BK;
            a0 = *(const float4*)&Wp[(size_t)lm0 * CC + k0 + lk0];
            a1 = *(const float4*)&Wp[(size_t)lm1 * CC + k0 + lk1];
            b0 = *(const float4*)&Xp[(size_t)lm0 * CC + k0 + lk0];
            b1 = *(const float4*)&Xp[(size_t)lm1 * CC + k0 + lk1];
        }

        // compute: 2 k8-steps over current buffer
#pragma unroll
        for (int s = 0; s < 2; s++) {
            uint32_t af[4][4], bf[4][2];
#pragma unroll
            for (int mt = 0; mt < 4; mt++) {
                const int mr = wm * 64 + mt * 16;
                af[mt][0] = As[cur][(mr + g) * APAD + s * 8 + tig];
                af[mt][1] = As[cur][(mr + g + 8) * APAD + s * 8 + tig];
                af[mt][2] = As[cur][(mr + g) * APAD + s * 8 + tig + 4];
                af[mt][3] = As[cur][(mr + g + 8) * APAD + s * 8 + tig + 4];
            }
#pragma unroll
            for (int nt = 0; nt < 4; nt++) {
                const int nr = wn * 32 + nt * 8;
                bf[nt][0] = Bs[cur][(nr + g) * APAD + s * 8 + tig];
                bf[nt][1] = Bs[cur][(nr + g) * APAD + s * 8 + tig + 4];
            }
#pragma unroll
            for (int mt = 0; mt < 4; mt++)
#pragma unroll
                for (int nt = 0; nt < 4; nt++)
                    mma_tf32(acc[mt][nt], af[mt], bf[nt]);
        }

        if (kt + 1 < NKT) {
            uint32_t* pa0 = &As[nxt][lm0 * APAD + lk0];
            pa0[0] = f2tf32(a0.x); pa0[1] = f2tf32(a0.y); pa0[2] = f2tf32(a0.z); pa0[3] = f2tf32(a0.w);
            uint32_t* pa1 = &As[nxt][lm1 * APAD + lk1];
            pa1[0] = f2tf32(a1.x); pa1[1] = f2tf32(a1.y); pa1[2] = f2tf32(a1.z); pa1[3] = f2tf32(a1.w);
            uint32_t* pb0 = &Bs[nxt][lm0 * APAD + lk0];
            pb0[0] = f2tf32(b0.x); pb0[1] = f2tf32(b0.y); pb0[2] = f2tf32(b0.z); pb0[3] = f2tf32(b0.w);
            uint32_t* pb1 = &Bs[nxt][lm1 * APAD + lk1];
            pb1[0] = f2tf32(b1.x); pb1[1] = f2tf32(b1.y); pb1[2] = f2tf32(b1.z); pb1[3] = f2tf32(b1.w);
        }
        __syncthreads();
    }

    // epilogue
#pragma unroll
    for (int mt = 0; mt < 4; mt++) {
        const int mA = m0 + wm * 64 + mt * 16 + g;      // rows g and g+8
        const float bvA = bias[mA], bvB = bias[mA + 8];
        float* oA = out + ((size_t)b * O + mA) * NN + n0;
        float* oB = oA + (size_t)8 * NN;
        const float* rA = RES ? res + ((size_t)b * O + mA) * NN + n0 : nullptr;
        const float* rB = RES ? rA + (size_t)8 * NN : nullptr;
#pragma unroll
        for (int nt = 0; nt < 4; nt++) {
            const int nc = wn * 32 + nt * 8 + tig * 2;
            float2 vA = make_float2(acc[mt][nt][0] + bvA, acc[mt][nt][1] + bvA);
            float2 vB = make_float2(acc[mt][nt][2] + bvB, acc[mt][nt][3] + bvB);
            if (RES) {
                float2 ra = *(const float2*)&rA[nc];
                float2 rb = *(const float2*)&rB[nc];
                vA.x += ra.x; vA.y += ra.y;
                vB.x += rb.x; vB.y += rb.y;
            }
            *(float2*)&oA[nc] = vA;
            *(float2*)&oB[nc] = vB;
        }
    }
}

// ---------------------------------------------------------------------------
// Flash attention fp32. Output TRANSPOSED: attT[b][n][c].
// ---------------------------------------------------------------------------
#define QST 132

__global__ __launch_bounds__(256, 1) void attn_kernel(
    const float* __restrict__ qkv, float* __restrict__ attT) {
    extern __shared__ float sm[];
    float* Qs = sm;
    float* Ks = Qs + 64 * QST;
    float* Vs = Ks + 64 * QST;
    float* Ps = Vs + 64 * QST;

    const int qb = blockIdx.x, h = blockIdx.y, b = blockIdx.z;
    const float* qg = qkv + ((size_t)b * 3 * CC + h * HD) * NN;
    const float* kg = qg + (size_t)CC * NN;
    const float* vg = kg + (size_t)CC * NN;

    const int tid = threadIdx.x;
    const int tx = tid % 16, ty = tid / 16;
    const float scale = 0.125f;

    for (int i = tid; i < 64 * 32; i += 256) {
        int d = i / 32, c4 = (i % 32) * 4;
        float4 v = *(const float4*)&qg[(size_t)d * NN + qb * 128 + c4];
        v.x *= scale; v.y *= scale; v.z *= scale; v.w *= scale;
        *(float4*)&Qs[d * QST + c4] = v;
    }

    float m_i[8], l_i[8], o[8][4];
#pragma unroll
    for (int i = 0; i < 8; i++) {
        m_i[i] = -1e30f; l_i[i] = 0.f;
#pragma unroll
        for (int j = 0; j < 4; j++) o[i][j] = 0.f;
    }

    for (int kb = 0; kb < 8; kb++) {
        __syncthreads();
        for (int i = tid; i < 64 * 32; i += 256) {
            int d = i / 32, c4 = (i % 32) * 4;
            *(float4*)&Ks[d * QST + c4] =
                *(const float4*)&kg[(size_t)d * NN + kb * 128 + c4];
            *(float4*)&Vs[d * QST + c4] =
                *(const float4*)&vg[(size_t)d * NN + kb * 128 + c4];
        }
        __syncthreads();

        float s[8][8];
#pragma unroll
        for (int i = 0; i < 8; i++)
#pragma unroll
            for (int j = 0; j < 8; j++) s[i][j] = 0.f;
#pragma unroll 8
        for (int d = 0; d < 64; d++) {
            float fa[8], fb[8];
            *(float4*)&fa[0] = *(float4*)&Qs[d * QST + ty * 8];
            *(float4*)&fa[4] = *(float4*)&Qs[d * QST + ty * 8 + 4];
            *(float4*)&fb[0] = *(float4*)&Ks[d * QST + tx * 8];
            *(float4*)&fb[4] = *(float4*)&Ks[d * QST + tx * 8 + 4];
#pragma unroll
            for (int i = 0; i < 8; i++)
#pragma unroll
                for (int j = 0; j < 8; j++) s[i][j] += fa[i] * fb[j];
        }

#pragma unroll
        for (int i = 0; i < 8; i++) {
            float rm = s[i][0];
#pragma unroll
            for (int j = 1; j < 8; j++) rm = fmaxf(rm, s[i][j]);
            rm = fmaxf(rm, __shfl_xor_sync(0xffffffffu, rm, 1, 16));
            rm = fmaxf(rm, __shfl_xor_sync(0xffffffffu, rm, 2, 16));
            rm = fmaxf(rm, __shfl_xor_sync(0xffffffffu, rm, 4, 16));
            rm = fmaxf(rm, __shfl_xor_sync(0xffffffffu, rm, 8, 16));
            float mnew = fmaxf(m_i[i], rm);
            float alpha = __expf(m_i[i] - mnew);
            m_i[i] = mnew;
            float rsum = 0.f;
#pragma unroll
            for (int j = 0; j < 8; j++) {
                s[i][j] = __expf(s[i][j] - mnew);
                rsum += s[i][j];
            }
            rsum += __shfl_xor_sync(0xffffffffu, rsum, 1, 16);
            rsum += __shfl_xor_sync(0xffffffffu, rsum, 2, 16);
            rsum += __shfl_xor_sync(0xffffffffu, rsum, 4, 16);
            rsum += __shfl_xor_sync(0xffffffffu, rsum, 8, 16);
            l_i[i] = l_i[i] * alpha + rsum;
#pragma unroll
            for (int j = 0; j < 4; j++) o[i][j] *= alpha;
            *(float4*)&Ps[(ty * 8 + i) * QST + tx * 8] =
                make_float4(s[i][0], s[i][1], s[i][2], s[i][3]);
            *(float4*)&Ps[(ty * 8 + i) * QST + tx * 8 + 4] =
                make_float4(s[i][4], s[i][5], s[i][6], s[i][7]);
        }
        __syncthreads();

#pragma unroll 4
        for (int kj = 0; kj < 128; kj++) {
            float vr[4];
#pragma unroll
            for (int j = 0; j < 4; j++) vr[j] = Vs[(tx + 16 * j) * QST + kj];
#pragma unroll
            for (int i = 0; i < 8; i++) {
                float p = Ps[(ty * 8 + i) * QST + kj];
#pragma unroll
                for (int j = 0; j < 4; j++) o[i][j] += p * vr[j];
            }
        }
    }

    float* og = attT + ((size_t)b * NN + qb * 128) * CC + h * HD;
#pragma unroll
    for (int i = 0; i < 8; i++) {
        float inv = 1.f / l_i[i];
        int qi = ty * 8 + i;
#pragma unroll
        for (int j = 0; j < 4; j++) {
            og[(size_t)qi * CC + tx + 16 * j] = o[i][j] * inv;
        }
    }
}

// ---------------------------------------------------------------------------
extern "C" void kernel_launch(void* const* d_in, const int* in_sizes, int n_in,
                              void* d_out, int out_size) {
    const float* x = (const float*)d_in[0];
    const float* gamma = (const float*)d_in[1];
    const float* beta = (const float*)d_in[2];
    const float* qkv_w = (const float*)d_in[3];
    const float* qkv_b = (const float*)d_in[4];
    const float* proj_w = (const float*)d_in[5];
    const float* proj_b = (const float*)d_in[6];
    float* out = (float*)d_out;

    float *xnT, *qkv, *attT;
    cudaGetSymbolAddress((void**)&xnT, g_xnT);
    cudaGetSymbolAddress((void**)&qkv, g_qkv);
    cudaGetSymbolAddress((void**)&attT, g_attT);

    // 1. GroupNorm (writes transposed [B,N,C])
    groupnorm_kernel<<<BQ * NG, 256>>>(x, gamma, beta, xnT);

    // 2. QKV GEMM (tf32 mma.sync)
    dim3 gq(NN / 128, (3 * CC) / 128, BQ);
    gemm_mma<false><<<gq, 256>>>(qkv_w, qkv_b, xnT, nullptr, qkv, 3 * CC);

    // 3. Flash attention fp32 (writes transposed [B,N,C])
    size_t shmem = (size_t)(3 * 64 * QST + 128 * QST) * sizeof(float);
    cudaFuncSetAttribute(attn_kernel,
                         cudaFuncAttributeMaxDynamicSharedMemorySize, (int)shmem);
    attn_kernel<<<dim3(NN / 128, NH, BQ), 256, shmem>>>(qkv, attT);

    // 4. Proj GEMM (tf32 mma.sync) + residual
    dim3 gp(NN / 128, CC / 128, BQ);
    gemm_mma<true><<<gp, 256>>>(proj_w, proj_b, attT, x, out, CC);
}

// round 4
// speedup vs baseline: 1.9581x; 1.3309x over previous
#include <cuda_runtime.h>
#include <cstdint>

#define BQ 16
#define CC 512
#define NN 1024
#define NH 8
#define HD 64
#define NG 32
#define CPG 16
#define EPSV 1e-5f

// ---------------------------------------------------------------------------
// mma.sync helpers (base PTX, works on compute_103 virtual arch)
// ---------------------------------------------------------------------------
__device__ __forceinline__ uint32_t f2tf32(float f) {
    uint32_t r;
    asm("cvt.rna.tf32.f32 %0, %1;" : "=r"(r) : "f"(f));
    return r;
}
__device__ __forceinline__ void mma_tf32(float* c, const uint32_t* a,
                                         const uint32_t* b) {
    asm volatile(
        "mma.sync.aligned.m16n8k8.row.col.f32.tf32.tf32.f32 "
        "{%0,%1,%2,%3}, {%4,%5,%6,%7}, {%8,%9}, {%0,%1,%2,%3};"
        : "+f"(c[0]), "+f"(c[1]), "+f"(c[2]), "+f"(c[3])
        : "r"(a[0]), "r"(a[1]), "r"(a[2]), "r"(a[3]), "r"(b[0]), "r"(b[1]));
}

// ---------------------------------------------------------------------------
// Scratch
// ---------------------------------------------------------------------------
__device__ float g_xnT[(size_t)BQ * NN * CC];       // [B,N,C]
__device__ float g_qkv[(size_t)BQ * 3 * CC * NN];   // [B,3C,N]
__device__ float g_attT[(size_t)BQ * NN * CC];      // [B,N,C]

// ---------------------------------------------------------------------------
// GroupNorm: one CTA per (b, g). Output TRANSPOSED: xnT[b][n][c].
// ---------------------------------------------------------------------------
__global__ __launch_bounds__(256) void groupnorm_kernel(
    const float* __restrict__ x, const float* __restrict__ gamma,
    const float* __restrict__ beta, float* __restrict__ xnT) {
    const int b = blockIdx.x / NG;
    const int g = blockIdx.x % NG;
    const float* px = x + ((size_t)b * CC + g * CPG) * NN;
    const int M = CPG * NN;

    float s = 0.f, ss = 0.f;
    for (int i = threadIdx.x; i < M / 4; i += blockDim.x) {
        float4 v = ((const float4*)px)[i];
        s += v.x + v.y + v.z + v.w;
        ss += v.x * v.x + v.y * v.y + v.z * v.z + v.w * v.w;
    }
    __shared__ float rs[32], rss[32];
    __shared__ float tile[16 * 129];
#pragma unroll
    for (int o = 16; o; o >>= 1) {
        s += __shfl_xor_sync(0xffffffffu, s, o);
        ss += __shfl_xor_sync(0xffffffffu, ss, o);
    }
    int wid = threadIdx.x / 32, lid = threadIdx.x % 32;
    if (lid == 0) { rs[wid] = s; rss[wid] = ss; }
    __syncthreads();
    if (wid == 0) {
        s = (lid < 8) ? rs[lid] : 0.f;
        ss = (lid < 8) ? rss[lid] : 0.f;
#pragma unroll
        for (int o = 16; o; o >>= 1) {
            s += __shfl_xor_sync(0xffffffffu, s, o);
            ss += __shfl_xor_sync(0xffffffffu, ss, o);
        }
        if (lid == 0) { rs[0] = s; rss[0] = ss; }
    }
    __syncthreads();
    const float mean = rs[0] / (float)M;
    const float var = rss[0] / (float)M - mean * mean;
    const float rstd = rsqrtf(var + EPSV);

    for (int n0 = 0; n0 < NN; n0 += 128) {
        __syncthreads();
#pragma unroll
        for (int rep = 0; rep < 8; rep++) {
            int idx = rep * 256 + threadIdx.x;
            int c = idx >> 7, n = idx & 127;
            float ga = gamma[g * CPG + c] * rstd;
            float be = beta[g * CPG + c];
            float v = px[(size_t)c * NN + n0 + n];
            tile[c * 129 + n] = (v - mean) * ga + be;
        }
        __syncthreads();
#pragma unroll
        for (int rep = 0; rep < 8; rep++) {
            int idx = rep * 256 + threadIdx.x;
            int n = idx >> 4, c = idx & 15;
            xnT[((size_t)b * NN + n0 + n) * CC + g * CPG + c] = tile[c * 129 + n];
        }
    }
}

// ---------------------------------------------------------------------------
// TF32 mma.sync GEMM (unchanged from Round 3).
// ---------------------------------------------------------------------------
#define BK 16
#define APAD 20

template <bool RES>
__global__ __launch_bounds__(256, 2) void gemm_mma(
    const float* __restrict__ W, const float* __restrict__ bias,
    const float* __restrict__ XT, const float* __restrict__ res,
    float* __restrict__ out, int O) {
    __shared__ uint32_t As[2][128 * APAD];
    __shared__ uint32_t Bs[2][128 * APAD];

    const int tid = threadIdx.x;
    const int wid = tid >> 5, lane = tid & 31;
    const int g = lane >> 2, tig = lane & 3;
    const int wm = wid >> 2, wn = wid & 3;
    const int b = blockIdx.z, n0 = blockIdx.x * 128, m0 = blockIdx.y * 128;
    const float* Xb = XT + (size_t)b * NN * CC;

    const int lm0 = tid >> 2, lk0 = (tid & 3) * 4;
    const int lm1 = (tid + 256) >> 2, lk1 = lk0;

    float acc[4][4][4];
#pragma unroll
    for (int i = 0; i < 4; i++)
#pragma unroll
        for (int j = 0; j < 4; j++)
#pragma unroll
            for (int e = 0; e < 4; e++) acc[i][j][e] = 0.f;

    const float* Wp = W + (size_t)m0 * CC;
    const float* Xp = Xb + (size_t)n0 * CC;

    {
        float4 a0 = *(const float4*)&Wp[(size_t)lm0 * CC + lk0];
        float4 a1 = *(const float4*)&Wp[(size_t)lm1 * CC + lk1];
        float4 b0 = *(const float4*)&Xp[(size_t)lm0 * CC + lk0];
        float4 b1 = *(const float4*)&Xp[(size_t)lm1 * CC + lk1];
        uint32_t* pa0 = &As[0][lm0 * APAD + lk0];
        pa0[0] = f2tf32(a0.x); pa0[1] = f2tf32(a0.y); pa0[2] = f2tf32(a0.z); pa0[3] = f2tf32(a0.w);
        uint32_t* pa1 = &As[0][lm1 * APAD + lk1];
        pa1[0] = f2tf32(a1.x); pa1[1] = f2tf32(a1.y); pa1[2] = f2tf32(a1.z); pa1[3] = f2tf32(a1.w);
        uint32_t* pb0 = &Bs[0][lm0 * APAD + lk0];
        pb0[0] = f2tf32(b0.x); pb0[1] = f2tf32(b0.y); pb0[2] = f2tf32(b0.z); pb0[3] = f2tf32(b0.w);
        uint32_t* pb1 = &Bs[0][lm1 * APAD + lk1];
        pb1[0] = f2tf32(b1.x); pb1[1] = f2tf32(b1.y); pb1[2] = f2tf32(b1.z); pb1[3] = f2tf32(b1.w);
    }
    __syncthreads();

    const int NKT = CC / BK;
    for (int kt = 0; kt < NKT; kt++) {
        const int cur = kt & 1, nxt = cur ^ 1;
        float4 a0, a1, b0, b1;
        if (kt + 1 < NKT) {
            const int k0 = (kt + 1) * BK;
            a0 = *(const float4*)&Wp[(size_t)lm0 * CC + k0 + lk0];
            a1 = *(const float4*)&Wp[(size_t)lm1 * CC + k0 + lk1];
            b0 = *(const float4*)&Xp[(size_t)lm0 * CC + k0 + lk0];
            b1 = *(const float4*)&Xp[(size_t)lm1 * CC + k0 + lk1];
        }

#pragma unroll
        for (int s = 0; s < 2; s++) {
            uint32_t af[4][4], bf[4][2];
#pragma unroll
            for (int mt = 0; mt < 4; mt++) {
                const int mr = wm * 64 + mt * 16;
                af[mt][0] = As[cur][(mr + g) * APAD + s * 8 + tig];
                af[mt][1] = As[cur][(mr + g + 8) * APAD + s * 8 + tig];
                af[mt][2] = As[cur][(mr + g) * APAD + s * 8 + tig + 4];
                af[mt][3] = As[cur][(mr + g + 8) * APAD + s * 8 + tig + 4];
            }
#pragma unroll
            for (int nt = 0; nt < 4; nt++) {
                const int nr = wn * 32 + nt * 8;
                bf[nt][0] = Bs[cur][(nr + g) * APAD + s * 8 + tig];
                bf[nt][1] = Bs[cur][(nr + g) * APAD + s * 8 + tig + 4];
            }
#pragma unroll
            for (int mt = 0; mt < 4; mt++)
#pragma unroll
                for (int nt = 0; nt < 4; nt++)
                    mma_tf32(acc[mt][nt], af[mt], bf[nt]);
        }

        if (kt + 1 < NKT) {
            uint32_t* pa0 = &As[nxt][lm0 * APAD + lk0];
            pa0[0] = f2tf32(a0.x); pa0[1] = f2tf32(a0.y); pa0[2] = f2tf32(a0.z); pa0[3] = f2tf32(a0.w);
            uint32_t* pa1 = &As[nxt][lm1 * APAD + lk1];
            pa1[0] = f2tf32(a1.x); pa1[1] = f2tf32(a1.y); pa1[2] = f2tf32(a1.z); pa1[3] = f2tf32(a1.w);
            uint32_t* pb0 = &Bs[nxt][lm0 * APAD + lk0];
            pb0[0] = f2tf32(b0.x); pb0[1] = f2tf32(b0.y); pb0[2] = f2tf32(b0.z); pb0[3] = f2tf32(b0.w);
            uint32_t* pb1 = &Bs[nxt][lm1 * APAD + lk1];
            pb1[0] = f2tf32(b1.x); pb1[1] = f2tf32(b1.y); pb1[2] = f2tf32(b1.z); pb1[3] = f2tf32(b1.w);
        }
        __syncthreads();
    }

#pragma unroll
    for (int mt = 0; mt < 4; mt++) {
        const int mA = m0 + wm * 64 + mt * 16 + g;
        const float bvA = bias[mA], bvB = bias[mA + 8];
        float* oA = out + ((size_t)b * O + mA) * NN + n0;
        float* oB = oA + (size_t)8 * NN;
        const float* rA = RES ? res + ((size_t)b * O + mA) * NN + n0 : nullptr;
        const float* rB = RES ? rA + (size_t)8 * NN : nullptr;
#pragma unroll
        for (int nt = 0; nt < 4; nt++) {
            const int nc = wn * 32 + nt * 8 + tig * 2;
            float2 vA = make_float2(acc[mt][nt][0] + bvA, acc[mt][nt][1] + bvA);
            float2 vB = make_float2(acc[mt][nt][2] + bvB, acc[mt][nt][3] + bvB);
            if (RES) {
                float2 ra = *(const float2*)&rA[nc];
                float2 rb = *(const float2*)&rB[nc];
                vA.x += ra.x; vA.y += ra.y;
                vB.x += rb.x; vB.y += rb.y;
            }
            *(float2*)&oA[nc] = vA;
            *(float2*)&oB[nc] = vB;
        }
    }
}

// ---------------------------------------------------------------------------
// Flash attention, TF32 mma.sync. CTA = (qb, h, b); 8 warps x 16 query rows.
// Qs/Ks: [128][68] tf32 (transposed to [n][d]); Vs: [64][132] native [dv][j];
// Ps: [128][132] tf32 (per-warp P round trip for fragment relayout).
// ---------------------------------------------------------------------------
#define QS_OFF 0
#define KS_OFF 8704
#define VS_OFF 17408
#define PS_OFF 25856
#define ATTN_SMEM ((25856 + 128 * 132) * 4)  // 171008 B

__global__ __launch_bounds__(256, 1) void attn_mma(
    const float* __restrict__ qkv, float* __restrict__ attT) {
    extern __shared__ uint32_t smw[];
    uint32_t* Qs = smw + QS_OFF;
    uint32_t* Ks = smw + KS_OFF;
    uint32_t* Vs = smw + VS_OFF;
    uint32_t* Ps = smw + PS_OFF;

    const int qb = blockIdx.x, h = blockIdx.y, b = blockIdx.z;
    const float* qg = qkv + ((size_t)b * 3 * CC + h * HD) * NN;
    const float* kg = qg + (size_t)CC * NN;
    const float* vg = kg + (size_t)CC * NN;

    const int tid = threadIdx.x, w = tid >> 5, lane = tid & 31;
    const int g = lane >> 2, tig = lane & 3;
    const int w16 = w * 16;

    // load Q transposed ([n][d]), pre-scaled
    for (int idx = tid; idx < 64 * 128; idx += 256) {
        int d = idx >> 7, n = idx & 127;
        Qs[n * 68 + d] = f2tf32(qg[(size_t)d * NN + qb * 128 + n] * 0.125f);
    }

    float m0 = -1e30f, m1 = -1e30f, l0 = 0.f, l1 = 0.f;
    float o[8][4];
#pragma unroll
    for (int nt = 0; nt < 8; nt++)
#pragma unroll
        for (int e = 0; e < 4; e++) o[nt][e] = 0.f;

    for (int kb = 0; kb < 8; kb++) {
        __syncthreads();  // prev PV done; Ks/Vs/Ps reusable (and Q visible)
        for (int idx = tid; idx < 64 * 128; idx += 256) {
            int d = idx >> 7, n = idx & 127;
            Ks[n * 68 + d] = f2tf32(kg[(size_t)d * NN + kb * 128 + n]);
            Vs[d * 132 + n] = f2tf32(vg[(size_t)d * NN + kb * 128 + n]);
        }
        __syncthreads();

        // S = Q K^T : warp tile 16 x 128, k-dim = d = 64
        float s[16][4];
#pragma unroll
        for (int nt = 0; nt < 16; nt++)
#pragma unroll
            for (int e = 0; e < 4; e++) s[nt][e] = 0.f;
#pragma unroll
        for (int ks = 0; ks < 8; ks++) {
            uint32_t af[4];
            af[0] = Qs[(w16 + g) * 68 + ks * 8 + tig];
            af[1] = Qs[(w16 + g + 8) * 68 + ks * 8 + tig];
            af[2] = Qs[(w16 + g) * 68 + ks * 8 + tig + 4];
            af[3] = Qs[(w16 + g + 8) * 68 + ks * 8 + tig + 4];
#pragma unroll
            for (int nt = 0; nt < 16; nt++) {
                uint32_t bf[2];
                bf[0] = Ks[(nt * 8 + g) * 68 + ks * 8 + tig];
                bf[1] = Ks[(nt * 8 + g) * 68 + ks * 8 + tig + 4];
                mma_tf32(s[nt], af, bf);
            }
        }

        // online softmax: thread's rows are g (e=0,1) and g+8 (e=2,3)
        float rm0 = -1e30f, rm1 = -1e30f;
#pragma unroll
        for (int nt = 0; nt < 16; nt++) {
            rm0 = fmaxf(rm0, fmaxf(s[nt][0], s[nt][1]));
            rm1 = fmaxf(rm1, fmaxf(s[nt][2], s[nt][3]));
        }
        rm0 = fmaxf(rm0, __shfl_xor_sync(0xffffffffu, rm0, 1));
        rm0 = fmaxf(rm0, __shfl_xor_sync(0xffffffffu, rm0, 2));
        rm1 = fmaxf(rm1, __shfl_xor_sync(0xffffffffu, rm1, 1));
        rm1 = fmaxf(rm1, __shfl_xor_sync(0xffffffffu, rm1, 2));
        const float mn0 = fmaxf(m0, rm0), mn1 = fmaxf(m1, rm1);
        const float al0 = __expf(m0 - mn0), al1 = __expf(m1 - mn1);
        m0 = mn0; m1 = mn1;
        float sum0 = 0.f, sum1 = 0.f;
#pragma unroll
        for (int nt = 0; nt < 16; nt++) {
            s[nt][0] = __expf(s[nt][0] - mn0);
            s[nt][1] = __expf(s[nt][1] - mn0);
            s[nt][2] = __expf(s[nt][2] - mn1);
            s[nt][3] = __expf(s[nt][3] - mn1);
            sum0 += s[nt][0] + s[nt][1];
            sum1 += s[nt][2] + s[nt][3];
        }
        sum0 += __shfl_xor_sync(0xffffffffu, sum0, 1);
        sum0 += __shfl_xor_sync(0xffffffffu, sum0, 2);
        sum1 += __shfl_xor_sync(0xffffffffu, sum1, 1);
        sum1 += __shfl_xor_sync(0xffffffffu, sum1, 2);
        l0 = l0 * al0 + sum0;
        l1 = l1 * al1 + sum1;
#pragma unroll
        for (int nt = 0; nt < 8; nt++) {
            o[nt][0] *= al0; o[nt][1] *= al0;
            o[nt][2] *= al1; o[nt][3] *= al1;
        }

        // store P (tf32) to own warp's rows
#pragma unroll
        for (int nt = 0; nt < 16; nt++) {
            uint32_t* p0 = &Ps[(w16 + g) * 132 + nt * 8 + 2 * tig];
            p0[0] = f2tf32(s[nt][0]); p0[1] = f2tf32(s[nt][1]);
            uint32_t* p1 = &Ps[(w16 + g + 8) * 132 + nt * 8 + 2 * tig];
            p1[0] = f2tf32(s[nt][2]); p1[1] = f2tf32(s[nt][3]);
        }
        __syncwarp();

        // O += P V^T : warp tile 16 x 64, k-dim = j = 128
#pragma unroll
        for (int ks = 0; ks < 16; ks++) {
            uint32_t af[4];
            af[0] = Ps[(w16 + g) * 132 + ks * 8 + tig];
            af[1] = Ps[(w16 + g + 8) * 132 + ks * 8 + tig];
            af[2] = Ps[(w16 + g) * 132 + ks * 8 + tig + 4];
            af[3] = Ps[(w16 + g + 8) * 132 + ks * 8 + tig + 4];
#pragma unroll
            for (int nt = 0; nt < 8; nt++) {
                uint32_t bf[2];
                bf[0] = Vs[(nt * 8 + g) * 132 + ks * 8 + tig];
                bf[1] = Vs[(nt * 8 + g) * 132 + ks * 8 + tig + 4];
                mma_tf32(o[nt], af, bf);
            }
        }
    }

    // epilogue: attT[b][qb*128 + row][h*64 + dv]
    const float inv0 = 1.f / l0, inv1 = 1.f / l1;
    float* og = attT + ((size_t)b * NN + qb * 128 + w16 + g) * CC + h * HD;
    float* og8 = og + (size_t)8 * CC;
#pragma unroll
    for (int nt = 0; nt < 8; nt++) {
        const int dc = nt * 8 + 2 * tig;
        *(float2*)&og[dc] = make_float2(o[nt][0] * inv0, o[nt][1] * inv0);
        *(float2*)&og8[dc] = make_float2(o[nt][2] * inv1, o[nt][3] * inv1);
    }
}

// ---------------------------------------------------------------------------
extern "C" void kernel_launch(void* const* d_in, const int* in_sizes, int n_in,
                              void* d_out, int out_size) {
    const float* x = (const float*)d_in[0];
    const float* gamma = (const float*)d_in[1];
    const float* beta = (const float*)d_in[2];
    const float* qkv_w = (const float*)d_in[3];
    const float* qkv_b = (const float*)d_in[4];
    const float* proj_w = (const float*)d_in[5];
    const float* proj_b = (const float*)d_in[6];
    float* out = (float*)d_out;

    float *xnT, *qkv, *attT;
    cudaGetSymbolAddress((void**)&xnT, g_xnT);
    cudaGetSymbolAddress((void**)&qkv, g_qkv);
    cudaGetSymbolAddress((void**)&attT, g_attT);

    // 1. GroupNorm (writes transposed [B,N,C])
    groupnorm_kernel<<<BQ * NG, 256>>>(x, gamma, beta, xnT);

    // 2. QKV GEMM (tf32 mma.sync)
    dim3 gq(NN / 128, (3 * CC) / 128, BQ);
    gemm_mma<false><<<gq, 256>>>(qkv_w, qkv_b, xnT, nullptr, qkv, 3 * CC);

    // 3. Flash attention (tf32 mma.sync, writes transposed [B,N,C])
    cudaFuncSetAttribute(attn_mma,
                         cudaFuncAttributeMaxDynamicSharedMemorySize, ATTN_SMEM);
    attn_mma<<<dim3(NN / 128, NH, BQ), 256, ATTN_SMEM>>>(qkv, attT);

    // 4. Proj GEMM (tf32 mma.sync) + residual
    dim3 gp(NN / 128, CC / 128, BQ);
    gemm_mma<true><<<gp, 256>>>(proj_w, proj_b, attT, x, out, CC);
}

// round 5
// speedup vs baseline: 2.5845x; 1.3199x over previous
#include <cuda_runtime.h>
#include <cstdint>

#define BQ 16
#define CC 512
#define NN 1024
#define NH 8
#define HD 64
#define NG 32
#define CPG 16
#define EPSV 1e-5f

// ---------------------------------------------------------------------------
// PTX helpers (base PTX only; compute_103-safe)
// ---------------------------------------------------------------------------
__device__ __forceinline__ uint32_t f2tf32(float f) {
    uint32_t r;
    asm("cvt.rna.tf32.f32 %0, %1;" : "=r"(r) : "f"(f));
    return r;
}
__device__ __forceinline__ void mma_tf32(float* c, const uint32_t* a,
                                         const uint32_t* b) {
    asm volatile(
        "mma.sync.aligned.m16n8k8.row.col.f32.tf32.tf32.f32 "
        "{%0,%1,%2,%3}, {%4,%5,%6,%7}, {%8,%9}, {%0,%1,%2,%3};"
        : "+f"(c[0]), "+f"(c[1]), "+f"(c[2]), "+f"(c[3])
        : "r"(a[0]), "r"(a[1]), "r"(a[2]), "r"(a[3]), "r"(b[0]), "r"(b[1]));
}
__device__ __forceinline__ void cp16(void* sdst, const void* gsrc) {
    uint32_t s = (uint32_t)__cvta_generic_to_shared(sdst);
    asm volatile("cp.async.cg.shared.global [%0], [%1], 16;" :: "r"(s), "l"(gsrc));
}
#define CP_COMMIT() asm volatile("cp.async.commit_group;")
#define CP_WAIT(n) asm volatile("cp.async.wait_group %0;" :: "n"(n))

// ---------------------------------------------------------------------------
// Scratch
// ---------------------------------------------------------------------------
__device__ uint32_t g_xnT[(size_t)BQ * NN * CC];   // [B,N,C] tf32 bits
__device__ float    g_qkv[(size_t)BQ * 3 * CC * NN];
__device__ uint32_t g_attT[(size_t)BQ * NN * CC];  // [B,N,C] tf32 bits
__device__ uint32_t g_wq[(size_t)3 * CC * CC];     // qkv_w tf32
__device__ uint32_t g_wp[(size_t)CC * CC];         // proj_w tf32

// ---------------------------------------------------------------------------
// weight -> tf32 pre-convert
// ---------------------------------------------------------------------------
__global__ void w2tf32(const float4* __restrict__ in, uint4* __restrict__ out,
                       int n4) {
    int i = blockIdx.x * 256 + threadIdx.x;
    if (i < n4) {
        float4 v = in[i];
        out[i] = make_uint4(f2tf32(v.x), f2tf32(v.y), f2tf32(v.z), f2tf32(v.w));
    }
}

// ---------------------------------------------------------------------------
// GroupNorm: one CTA per (b, g). Output TRANSPOSED tf32 bits: xnT[b][n][c].
// ---------------------------------------------------------------------------
__global__ __launch_bounds__(256) void groupnorm_kernel(
    const float* __restrict__ x, const float* __restrict__ gamma,
    const float* __restrict__ beta, uint32_t* __restrict__ xnT) {
    const int b = blockIdx.x / NG;
    const int g = blockIdx.x % NG;
    const float* px = x + ((size_t)b * CC + g * CPG) * NN;
    const int M = CPG * NN;

    float s = 0.f, ss = 0.f;
    for (int i = threadIdx.x; i < M / 4; i += blockDim.x) {
        float4 v = ((const float4*)px)[i];
        s += v.x + v.y + v.z + v.w;
        ss += v.x * v.x + v.y * v.y + v.z * v.z + v.w * v.w;
    }
    __shared__ float rs[32], rss[32];
    __shared__ float tile[16 * 129];
#pragma unroll
    for (int o = 16; o; o >>= 1) {
        s += __shfl_xor_sync(0xffffffffu, s, o);
        ss += __shfl_xor_sync(0xffffffffu, ss, o);
    }
    int wid = threadIdx.x / 32, lid = threadIdx.x % 32;
    if (lid == 0) { rs[wid] = s; rss[wid] = ss; }
    __syncthreads();
    if (wid == 0) {
        s = (lid < 8) ? rs[lid] : 0.f;
        ss = (lid < 8) ? rss[lid] : 0.f;
#pragma unroll
        for (int o = 16; o; o >>= 1) {
            s += __shfl_xor_sync(0xffffffffu, s, o);
            ss += __shfl_xor_sync(0xffffffffu, ss, o);
        }
        if (lid == 0) { rs[0] = s; rss[0] = ss; }
    }
    __syncthreads();
    const float mean = rs[0] / (float)M;
    const float var = rss[0] / (float)M - mean * mean;
    const float rstd = rsqrtf(var + EPSV);

    for (int n0 = 0; n0 < NN; n0 += 128) {
        __syncthreads();
#pragma unroll
        for (int rep = 0; rep < 8; rep++) {
            int idx = rep * 256 + threadIdx.x;
            int c = idx >> 7, n = idx & 127;
            float ga = gamma[g * CPG + c] * rstd;
            float be = beta[g * CPG + c];
            float v = px[(size_t)c * NN + n0 + n];
            tile[c * 129 + n] = (v - mean) * ga + be;
        }
        __syncthreads();
#pragma unroll
        for (int rep = 0; rep < 8; rep++) {
            int idx = rep * 256 + threadIdx.x;
            int n = idx >> 4, c = idx & 15;
            xnT[((size_t)b * NN + n0 + n) * CC + g * CPG + c] =
                f2tf32(tile[c * 129 + n]);
        }
    }
}

// ---------------------------------------------------------------------------
// TF32 mma.sync GEMM, cp.async pipeline, pre-converted tf32 operands.
// out[b,m,n] = sum_k W[m,k]*XT[b,n,k] + bias[m] (+res)
// CTA 128x128, BK=16, 8 warps (2m x 4n), warp tile 64x32.
// ---------------------------------------------------------------------------
#define BK 16
#define APAD 20

template <bool RES>
__global__ __launch_bounds__(256, 2) void gemm_mma(
    const uint32_t* __restrict__ W, const float* __restrict__ bias,
    const uint32_t* __restrict__ XT, const float* __restrict__ res,
    float* __restrict__ out, int O) {
    __shared__ uint32_t As[2][128 * APAD];
    __shared__ uint32_t Bs[2][128 * APAD];

    const int tid = threadIdx.x;
    const int wid = tid >> 5, lane = tid & 31;
    const int g = lane >> 2, tig = lane & 3;
    const int wm = wid >> 2, wn = wid & 3;
    const int b = blockIdx.z, n0 = blockIdx.x * 128, m0 = blockIdx.y * 128;

    const int lm0 = tid >> 2, lk0 = (tid & 3) * 4;
    const int lm1 = lm0 + 64;

    float acc[4][4][4];
#pragma unroll
    for (int i = 0; i < 4; i++)
#pragma unroll
        for (int j = 0; j < 4; j++)
#pragma unroll
            for (int e = 0; e < 4; e++) acc[i][j][e] = 0.f;

    const uint32_t* Wp = W + (size_t)m0 * CC;
    const uint32_t* Xp = XT + (size_t)b * NN * CC + (size_t)n0 * CC;

    // issue cp.async for chunk into buffer
    auto issue = [&](int buf, int k0) {
        cp16(&As[buf][lm0 * APAD + lk0], &Wp[(size_t)lm0 * CC + k0 + lk0]);
        cp16(&As[buf][lm1 * APAD + lk0], &Wp[(size_t)lm1 * CC + k0 + lk0]);
        cp16(&Bs[buf][lm0 * APAD + lk0], &Xp[(size_t)lm0 * CC + k0 + lk0]);
        cp16(&Bs[buf][lm1 * APAD + lk0], &Xp[(size_t)lm1 * CC + k0 + lk0]);
    };

    issue(0, 0);
    CP_COMMIT();

    const int NKT = CC / BK;  // 32
    for (int kt = 0; kt < NKT; kt++) {
        const int cur = kt & 1;
        if (kt + 1 < NKT) {
            issue(cur ^ 1, (kt + 1) * BK);
            CP_COMMIT();
            CP_WAIT(1);
        } else {
            CP_WAIT(0);
        }
        __syncthreads();

#pragma unroll
        for (int s = 0; s < 2; s++) {
            uint32_t af[4][4], bf[4][2];
#pragma unroll
            for (int mt = 0; mt < 4; mt++) {
                const int mr = wm * 64 + mt * 16;
                af[mt][0] = As[cur][(mr + g) * APAD + s * 8 + tig];
                af[mt][1] = As[cur][(mr + g + 8) * APAD + s * 8 + tig];
                af[mt][2] = As[cur][(mr + g) * APAD + s * 8 + tig + 4];
                af[mt][3] = As[cur][(mr + g + 8) * APAD + s * 8 + tig + 4];
            }
#pragma unroll
            for (int nt = 0; nt < 4; nt++) {
                const int nr = wn * 32 + nt * 8;
                bf[nt][0] = Bs[cur][(nr + g) * APAD + s * 8 + tig];
                bf[nt][1] = Bs[cur][(nr + g) * APAD + s * 8 + tig + 4];
            }
#pragma unroll
            for (int mt = 0; mt < 4; mt++)
#pragma unroll
                for (int nt = 0; nt < 4; nt++)
                    mma_tf32(acc[mt][nt], af[mt], bf[nt]);
        }
        __syncthreads();
    }

#pragma unroll
    for (int mt = 0; mt < 4; mt++) {
        const int mA = m0 + wm * 64 + mt * 16 + g;
        const float bvA = bias[mA], bvB = bias[mA + 8];
        float* oA = out + ((size_t)b * O + mA) * NN + n0;
        float* oB = oA + (size_t)8 * NN;
        const float* rA = RES ? res + ((size_t)b * O + mA) * NN + n0 : nullptr;
        const float* rB = RES ? rA + (size_t)8 * NN : nullptr;
#pragma unroll
        for (int nt = 0; nt < 4; nt++) {
            const int nc = wn * 32 + nt * 8 + tig * 2;
            float2 vA = make_float2(acc[mt][nt][0] + bvA, acc[mt][nt][1] + bvA);
            float2 vB = make_float2(acc[mt][nt][2] + bvB, acc[mt][nt][3] + bvB);
            if (RES) {
                float2 ra = *(const float2*)&rA[nc];
                float2 rb = *(const float2*)&rB[nc];
                vA.x += ra.x; vA.y += ra.y;
                vB.x += rb.x; vB.y += rb.y;
            }
            *(float2*)&oA[nc] = vA;
            *(float2*)&oB[nc] = vB;
        }
    }
}

// ---------------------------------------------------------------------------
// Flash attention, TF32 mma.sync, shuffle-based P relayout (no P SMEM).
// SMEM: Qs/Ks [128][68], Vs [64][132]  -> 103424 B, 2 CTAs/SM.
// ---------------------------------------------------------------------------
#define QS_OFF 0
#define KS_OFF 8704
#define VS_OFF 17408
#define ATTN_SMEM ((17408 + 64 * 132) * 4)  // 103424 B

__global__ __launch_bounds__(256, 2) void attn_mma(
    const float* __restrict__ qkv, uint32_t* __restrict__ attT) {
    extern __shared__ uint32_t smw[];
    uint32_t* Qs = smw + QS_OFF;
    uint32_t* Ks = smw + KS_OFF;
    uint32_t* Vs = smw + VS_OFF;

    const int qb = blockIdx.x, h = blockIdx.y, b = blockIdx.z;
    const float* qg = qkv + ((size_t)b * 3 * CC + h * HD) * NN;
    const float* kg = qg + (size_t)CC * NN;
    const float* vg = kg + (size_t)CC * NN;

    const int tid = threadIdx.x, lane = tid & 31;
    const int g = lane >> 2, tig = lane & 3;
    const int w16 = (tid >> 5) * 16;
    const int src0 = (lane & ~3) | (tig >> 1);
    const int src2 = src0 + 2;
    const bool odd = tig & 1;

    // load Q transposed ([n][d]), pre-scaled, tf32
    for (int idx = tid; idx < 64 * 128; idx += 256) {
        int d = idx >> 7, n = idx & 127;
        Qs[n * 68 + d] = f2tf32(qg[(size_t)d * NN + qb * 128 + n] * 0.125f);
    }

    float m0 = -1e30f, m1 = -1e30f, l0 = 0.f, l1 = 0.f;
    float o[8][4];
#pragma unroll
    for (int nt = 0; nt < 8; nt++)
#pragma unroll
        for (int e = 0; e < 4; e++) o[nt][e] = 0.f;

    for (int kb = 0; kb < 8; kb++) {
        __syncthreads();  // prev PV reads done; (first iter: Q stores done)
        for (int idx = tid; idx < 64 * 128; idx += 256) {
            int d = idx >> 7, n = idx & 127;
            Ks[n * 68 + d] = f2tf32(kg[(size_t)d * NN + kb * 128 + n]);
            Vs[d * 132 + n] = f2tf32(vg[(size_t)d * NN + kb * 128 + n]);
        }
        __syncthreads();

        // S = Q K^T : warp tile 16 x 128, k-dim = d = 64
        float s[16][4];
#pragma unroll
        for (int nt = 0; nt < 16; nt++)
#pragma unroll
            for (int e = 0; e < 4; e++) s[nt][e] = 0.f;
#pragma unroll
        for (int ks = 0; ks < 8; ks++) {
            uint32_t af[4];
            af[0] = Qs[(w16 + g) * 68 + ks * 8 + tig];
            af[1] = Qs[(w16 + g + 8) * 68 + ks * 8 + tig];
            af[2] = Qs[(w16 + g) * 68 + ks * 8 + tig + 4];
            af[3] = Qs[(w16 + g + 8) * 68 + ks * 8 + tig + 4];
#pragma unroll
            for (int nt = 0; nt < 16; nt++) {
                uint32_t bf[2];
                bf[0] = Ks[(nt * 8 + g) * 68 + ks * 8 + tig];
                bf[1] = Ks[(nt * 8 + g) * 68 + ks * 8 + tig + 4];
                mma_tf32(s[nt], af, bf);
            }
        }

        // online softmax: thread's rows are g (e=0,1) and g+8 (e=2,3)
        float rm0 = -1e30f, rm1 = -1e30f;
#pragma unroll
        for (int nt = 0; nt < 16; nt++) {
            rm0 = fmaxf(rm0, fmaxf(s[nt][0], s[nt][1]));
            rm1 = fmaxf(rm1, fmaxf(s[nt][2], s[nt][3]));
        }
        rm0 = fmaxf(rm0, __shfl_xor_sync(0xffffffffu, rm0, 1));
        rm0 = fmaxf(rm0, __shfl_xor_sync(0xffffffffu, rm0, 2));
        rm1 = fmaxf(rm1, __shfl_xor_sync(0xffffffffu, rm1, 1));
        rm1 = fmaxf(rm1, __shfl_xor_sync(0xffffffffu, rm1, 2));
        const float mn0 = fmaxf(m0, rm0), mn1 = fmaxf(m1, rm1);
        const float al0 = __expf(m0 - mn0), al1 = __expf(m1 - mn1);
        m0 = mn0; m1 = mn1;
        float sum0 = 0.f, sum1 = 0.f;
#pragma unroll
        for (int nt = 0; nt < 16; nt++) {
            s[nt][0] = __expf(s[nt][0] - mn0);
            s[nt][1] = __expf(s[nt][1] - mn0);
            s[nt][2] = __expf(s[nt][2] - mn1);
            s[nt][3] = __expf(s[nt][3] - mn1);
            sum0 += s[nt][0] + s[nt][1];
            sum1 += s[nt][2] + s[nt][3];
        }
        sum0 += __shfl_xor_sync(0xffffffffu, sum0, 1);
        sum0 += __shfl_xor_sync(0xffffffffu, sum0, 2);
        sum1 += __shfl_xor_sync(0xffffffffu, sum1, 1);
        sum1 += __shfl_xor_sync(0xffffffffu, sum1, 2);
        l0 = l0 * al0 + sum0;
        l1 = l1 * al1 + sum1;
#pragma unroll
        for (int nt = 0; nt < 8; nt++) {
            o[nt][0] *= al0; o[nt][1] *= al0;
            o[nt][2] *= al1; o[nt][3] *= al1;
        }

        // O += P V^T : shuffle C-frag -> A-frag per 8-col block (k-step)
#pragma unroll
        for (int nt = 0; nt < 16; nt++) {
            float x0 = __shfl_sync(0xffffffffu, s[nt][0], src0);
            float x1 = __shfl_sync(0xffffffffu, s[nt][1], src0);
            float x2 = __shfl_sync(0xffffffffu, s[nt][2], src0);
            float x3 = __shfl_sync(0xffffffffu, s[nt][3], src0);
            float y0 = __shfl_sync(0xffffffffu, s[nt][0], src2);
            float y1 = __shfl_sync(0xffffffffu, s[nt][1], src2);
            float y2 = __shfl_sync(0xffffffffu, s[nt][2], src2);
            float y3 = __shfl_sync(0xffffffffu, s[nt][3], src2);
            uint32_t af[4];
            af[0] = f2tf32(odd ? x1 : x0);  // P(g,     nt*8+tig)
            af[1] = f2tf32(odd ? x3 : x2);  // P(g+8,   nt*8+tig)
            af[2] = f2tf32(odd ? y1 : y0);  // P(g,     nt*8+tig+4)
            af[3] = f2tf32(odd ? y3 : y2);  // P(g+8,   nt*8+tig+4)
#pragma unroll
            for (int nv = 0; nv < 8; nv++) {
                uint32_t bf[2];
                bf[0] = Vs[(nv * 8 + g) * 132 + nt * 8 + tig];
                bf[1] = Vs[(nv * 8 + g) * 132 + nt * 8 + tig + 4];
                mma_tf32(o[nv], af, bf);
            }
        }
    }

    // epilogue: attT[b][qb*128 + row][h*64 + dv]  (tf32 bits)
    const float inv0 = 1.f / l0, inv1 = 1.f / l1;
    uint32_t* og = attT + ((size_t)b * NN + qb * 128 + w16 + g) * CC + h * HD;
    uint32_t* og8 = og + (size_t)8 * CC;
#pragma unroll
    for (int nt = 0; nt < 8; nt++) {
        const int dc = nt * 8 + 2 * tig;
        og[dc]      = f2tf32(o[nt][0] * inv0);
        og[dc + 1]  = f2tf32(o[nt][1] * inv0);
        og8[dc]     = f2tf32(o[nt][2] * inv1);
        og8[dc + 1] = f2tf32(o[nt][3] * inv1);
    }
}

// ---------------------------------------------------------------------------
extern "C" void kernel_launch(void* const* d_in, const int* in_sizes, int n_in,
                              void* d_out, int out_size) {
    const float* x = (const float*)d_in[0];
    const float* gamma = (const float*)d_in[1];
    const float* beta = (const float*)d_in[2];
    const float* qkv_w = (const float*)d_in[3];
    const float* qkv_b = (const float*)d_in[4];
    const float* proj_w = (const float*)d_in[5];
    const float* proj_b = (const float*)d_in[6];
    float* out = (float*)d_out;

    uint32_t *xnT, *attT, *wq, *wp;
    float* qkv;
    cudaGetSymbolAddress((void**)&xnT, g_xnT);
    cudaGetSymbolAddress((void**)&qkv, g_qkv);
    cudaGetSymbolAddress((void**)&attT, g_attT);
    cudaGetSymbolAddress((void**)&wq, g_wq);
    cudaGetSymbolAddress((void**)&wp, g_wp);

    // 0. weight pre-conversion to tf32
    w2tf32<<<(3 * CC * CC / 4 + 255) / 256, 256>>>((const float4*)qkv_w,
                                                   (uint4*)wq, 3 * CC * CC / 4);
    w2tf32<<<(CC * CC / 4 + 255) / 256, 256>>>((const float4*)proj_w,
                                               (uint4*)wp, CC * CC / 4);

    // 1. GroupNorm (writes transposed tf32 [B,N,C])
    groupnorm_kernel<<<BQ * NG, 256>>>(x, gamma, beta, xnT);

    // 2. QKV GEMM
    dim3 gq(NN / 128, (3 * CC) / 128, BQ);
    gemm_mma<false><<<gq, 256>>>(wq, qkv_b, xnT, nullptr, qkv, 3 * CC);

    // 3. Flash attention (writes transposed tf32 [B,N,C])
    cudaFuncSetAttribute(attn_mma,
                         cudaFuncAttributeMaxDynamicSharedMemorySize, ATTN_SMEM);
    attn_mma<<<dim3(NN / 128, NH, BQ), 256, ATTN_SMEM>>>(qkv, attT);

    // 4. Proj GEMM + residual
    dim3 gp(NN / 128, CC / 128, BQ);
    gemm_mma<true><<<gp, 256>>>(wp, proj_b, attT, x, out, CC);
}